// round 15
// baseline (speedup 1.0000x reference)
#include <cuda_runtime.h>
#include <cuda_bf16.h>

// Problem constants (from reference)
#define BATCH 1024
#define DDIM  512
#define FDIM  4096

#define THREADS      256
#define INIT_BLOCKS  512   // 512*256 float4 == B*D/4 exactly

// Self-resetting cross-block flags (no allocation; __device__ globals).
__device__ unsigned int g_init_done = 0;  // init blocks completed
__device__ unsigned int g_done      = 0;  // all blocks completed (for reset)

// Fused kernel: blocks [0, INIT_BLOCKS) initialize out = bias + mask and
// release-signal; blocks [INIT_BLOCKS, ...) front-issue their stream loads,
// weight gathers and products, then wait for the signal and fire atomics.
// The last block to finish resets both counters so every graph replay sees
// identical initial state (deterministic).
__global__ __launch_bounds__(THREADS)
void tied_fused_kernel(const float4* __restrict__ vals4,
                       const int4* __restrict__ b4,
                       const int4* __restrict__ d4,
                       const int4* __restrict__ f4,
                       const float* __restrict__ w,
                       const float4* __restrict__ bias4,
                       const float4* __restrict__ mask4,
                       float* __restrict__ out,
                       int n4, int total4) {
    const int tid = threadIdx.x;

    if (blockIdx.x < INIT_BLOCKS) {
        // ---- init path: out = bias + mask ----
        int i = blockIdx.x * THREADS + tid;
        if (i < total4) {
            float4 m = mask4[i];
            float4 bv = __ldg(&bias4[i & (DDIM / 4 - 1)]);  // D/4 = 128
            m.x += bv.x; m.y += bv.y; m.z += bv.z; m.w += bv.w;
            ((float4*)out)[i] = m;
        }
        __threadfence();          // make writes visible before the release
        __syncthreads();
        if (tid == 0) atomicAdd(&g_init_done, 1u);
    } else {
        // ---- scatter path ----
        const int i = (blockIdx.x - INIT_BLOCKS) * THREADS + tid;
        bool active = (i < n4);

        float4 v;  int4 bi, di, fi;
        float c0 = 0.f, c1 = 0.f, c2 = 0.f, c3 = 0.f;
        if (active) {
            // front-batched loads (4x LDG.128) — overlap with init work
            v  = vals4[i];
            bi = b4[i];
            di = d4[i];
            fi = f4[i];
            c0 = v.x * __ldg(&w[fi.x]);
            c1 = v.y * __ldg(&w[fi.y]);
            c2 = v.z * __ldg(&w[fi.z]);
            c3 = v.w * __ldg(&w[fi.w]);
        }

        // Wait until all init blocks have signalled.
        if (tid == 0) {
            while (atomicAdd(&g_init_done, 0u) < INIT_BLOCKS) {
                __nanosleep(64);
            }
        }
        __syncthreads();
        __threadfence();          // acquire: init writes now visible to atomics

        if (active) {
            atomicAdd(&out[bi.x * DDIM + di.x], c0);
            atomicAdd(&out[bi.y * DDIM + di.y], c1);
            atomicAdd(&out[bi.z * DDIM + di.z], c2);
            atomicAdd(&out[bi.w * DDIM + di.w], c3);
        }
    }

    // ---- self-reset: last finishing block zeroes both counters ----
    __syncthreads();
    if (tid == 0) {
        unsigned int t = atomicAdd(&g_done, 1u);
        if (t == gridDim.x - 1u) {
            g_init_done = 0u;
            g_done = 0u;
            __threadfence();
        }
    }
}

// Tail handler for NNZ not divisible by 4 (defensive; NNZ=10M is divisible,
// so this never launches in practice).
__global__ __launch_bounds__(THREADS)
void tied_scatter_tail_kernel(const float* __restrict__ vals,
                              const int* __restrict__ b,
                              const int* __restrict__ d,
                              const int* __restrict__ f,
                              const float* __restrict__ w,
                              float* __restrict__ out,
                              int start, int n) {
    int i = start + blockIdx.x * blockDim.x + threadIdx.x;
    if (i >= n) return;
    atomicAdd(&out[b[i] * DDIM + d[i]], vals[i] * __ldg(&w[f[i]]));
}

extern "C" void kernel_launch(void* const* d_in, const int* in_sizes, int n_in,
                              void* d_out, int out_size) {
    // metadata order: values, b_idx, d_idx, f_idx, weight, bias, mask
    const float* values = (const float*)d_in[0];
    const int*   b_idx  = (const int*)d_in[1];
    const int*   d_idx  = (const int*)d_in[2];
    const int*   f_idx  = (const int*)d_in[3];
    const float* weight = (const float*)d_in[4];
    const float* bias   = (const float*)d_in[5];
    const float* mask   = (const float*)d_in[6];
    float* out = (float*)d_out;

    const int nnz = in_sizes[0];
    const int n4 = nnz / 4;
    const int total4 = out_size / 4;              // 131072 = INIT_BLOCKS*256

    int scatter_blocks = (n4 + THREADS - 1) / THREADS;   // ~9766
    int blocks = INIT_BLOCKS + scatter_blocks;           // ~10278

    tied_fused_kernel<<<blocks, THREADS>>>((const float4*)values,
                                           (const int4*)b_idx,
                                           (const int4*)d_idx,
                                           (const int4*)f_idx,
                                           weight,
                                           (const float4*)bias,
                                           (const float4*)mask,
                                           out, n4, total4);

    int tail_start = n4 * 4;
    int tail = nnz - tail_start;
    if (tail > 0) {
        tied_scatter_tail_kernel<<<1, 256>>>(values, b_idx, d_idx, f_idx,
                                             weight, out, tail_start, nnz);
    }
}

// round 16
// speedup vs baseline: 1.5005x; 1.5005x over previous
#include <cuda_runtime.h>
#include <cuda_bf16.h>

// Problem constants (from reference)
#define BATCH 1024
#define DDIM  512
#define FDIM  4096

// out[b*D+d] = bias[d] + mask[b*D+d], vectorized float4, one-shot grid.
__global__ __launch_bounds__(256)
void tied_init_kernel(float4* __restrict__ out4,
                      const float4* __restrict__ bias4,
                      const float4* __restrict__ mask4,
                      int total4) {
    int i = blockIdx.x * blockDim.x + threadIdx.x;
    if (i >= total4) return;
    float4 m = mask4[i];
    float4 bv = __ldg(&bias4[i & (DDIM / 4 - 1)]);   // D/4 = 128, power of 2
    m.x += bv.x; m.y += bv.y; m.z += bv.z; m.w += bv.w;
    out4[i] = m;
}

// Final configuration (best measured scatter: 65.66us). One 4-nnz packet per
// thread: 4 front-batched LDG.128s (values + 3 index streams), L1-resident
// weight gathers, fire-and-forget atomicAdd (REDG) into the L2-resident 2MB
// output. Grid ~9766 one-shot blocks; hardware wave scheduling absorbs the
// per-SM REDG finish-time spread. Scatter is pinned at the per-SM atomic
// lane-issue floor (~46us of pure REDG lane work + stream processing);
// measured levers beyond this config were all neutral or regressions.
__global__ __launch_bounds__(256)
void tied_scatter_kernel(const float4* __restrict__ vals4,
                         const int4* __restrict__ b4,
                         const int4* __restrict__ d4,
                         const int4* __restrict__ f4,
                         const float* __restrict__ w,
                         float* __restrict__ out,
                         int n4) {
    const int i = blockIdx.x * blockDim.x + threadIdx.x;
    if (i >= n4) return;

    // ---- front-batched loads (4x LDG.128) ----
    float4 v  = vals4[i];
    int4  bi = b4[i];
    int4  di = d4[i];
    int4  fi = f4[i];

    // weight gathers: 16KB table, L1-resident
    float w0 = __ldg(&w[fi.x]);
    float w1 = __ldg(&w[fi.y]);
    float w2 = __ldg(&w[fi.z]);
    float w3 = __ldg(&w[fi.w]);

    atomicAdd(&out[bi.x * DDIM + di.x], v.x * w0);
    atomicAdd(&out[bi.y * DDIM + di.y], v.y * w1);
    atomicAdd(&out[bi.z * DDIM + di.z], v.z * w2);
    atomicAdd(&out[bi.w * DDIM + di.w], v.w * w3);
}

// Tail handler for NNZ not divisible by 4 (defensive; NNZ=10M is divisible,
// so this never launches in practice).
__global__ __launch_bounds__(256)
void tied_scatter_tail_kernel(const float* __restrict__ vals,
                              const int* __restrict__ b,
                              const int* __restrict__ d,
                              const int* __restrict__ f,
                              const float* __restrict__ w,
                              float* __restrict__ out,
                              int start, int n) {
    int i = start + blockIdx.x * blockDim.x + threadIdx.x;
    if (i >= n) return;
    atomicAdd(&out[b[i] * DDIM + d[i]], vals[i] * __ldg(&w[f[i]]));
}

extern "C" void kernel_launch(void* const* d_in, const int* in_sizes, int n_in,
                              void* d_out, int out_size) {
    // metadata order: values, b_idx, d_idx, f_idx, weight, bias, mask
    const float* values = (const float*)d_in[0];
    const int*   b_idx  = (const int*)d_in[1];
    const int*   d_idx  = (const int*)d_in[2];
    const int*   f_idx  = (const int*)d_in[3];
    const float* weight = (const float*)d_in[4];
    const float* bias   = (const float*)d_in[5];
    const float* mask   = (const float*)d_in[6];
    float* out = (float*)d_out;

    const int nnz = in_sizes[0];
    const int THREADS = 256;

    // 1) init: out = bias + mask  (out_size = B*D = 524288, /4 = 131072)
    {
        int total4 = out_size / 4;
        int blocks = (total4 + THREADS - 1) / THREADS;   // 512 blocks, one-shot
        tied_init_kernel<<<blocks, THREADS>>>((float4*)out,
                                              (const float4*)bias,
                                              (const float4*)mask,
                                              total4);
    }

    // 2) scatter: one 4-nnz packet per thread, grid ~9766 blocks
    {
        int n4 = nnz / 4;
        int blocks = (n4 + THREADS - 1) / THREADS;
        tied_scatter_kernel<<<blocks, THREADS>>>((const float4*)values,
                                                 (const int4*)b_idx,
                                                 (const int4*)d_idx,
                                                 (const int4*)f_idx,
                                                 weight, out, n4);
        int tail_start = n4 * 4;
        int tail = nnz - tail_start;
        if (tail > 0) {
            tied_scatter_tail_kernel<<<1, 256>>>(values, b_idx, d_idx, f_idx,
                                                 weight, out, tail_start, nnz);
        }
    }
}